// round 17
// baseline (speedup 1.0000x reference)
#include <cuda_runtime.h>
#include <cuda_bf16.h>
#include <math.h>
#include <cstdint>

// ---------------------------------------------------------------- dims
#define B_   256
#define T1_  128
#define S_   128
#define A_   32
#define H_   1024
#define E_   1024

#define O_B_SZ   (B_ * T1_ * H_)
#define O_S_SZ   (B_ * T1_ * S_)
#define SSTRIDE  (T1_ * S_)               // 16384
#define BSTRIDE  (T1_ * H_)               // 131072

// ---------------------------------------------------------------- scratch
__device__ float g_OB [(size_t)B_ * T1_ * H_];  // o @ W_bpos_o^T + b_bpos
__device__ float g_x  [B_ * H_];
__device__ float g_G  [B_ * 6 * H_];
__device__ float g_HPQ[B_ * 2 * H_];

// ---------------------------------------------------------------- helpers
__device__ __forceinline__ uint32_t smem_u32(const void* p) {
    uint32_t a;
    asm("{ .reg .u64 t; cvta.to.shared.u64 t, %1; cvt.u32.u64 %0, t; }" : "=r"(a) : "l"(p));
    return a;
}

// 8 fp32 -> hi/lo bf16 packs (hi = rn(x), lo = rn(x - hi)); fp32 accum recovers ~2^-16
__device__ __forceinline__ void cvt_pack8(const float* v, uint4& ph, uint4& pl) {
    unsigned hb[4], lb[4];
#pragma unroll
    for (int i = 0; i < 4; i++) {
        float x0 = v[2*i], x1 = v[2*i+1];
        __nv_bfloat16 h0 = __float2bfloat16(x0);
        __nv_bfloat16 h1 = __float2bfloat16(x1);
        __nv_bfloat16 l0 = __float2bfloat16(x0 - __bfloat162float(h0));
        __nv_bfloat16 l1 = __float2bfloat16(x1 - __bfloat162float(h1));
        hb[i] = (unsigned)__bfloat16_as_ushort(h0) | ((unsigned)__bfloat16_as_ushort(h1) << 16);
        lb[i] = (unsigned)__bfloat16_as_ushort(l0) | ((unsigned)__bfloat16_as_ushort(l1) << 16);
    }
    ph = make_uint4(hb[0], hb[1], hb[2], hb[3]);
    pl = make_uint4(lb[0], lb[1], lb[2], lb[3]);
}

__device__ __forceinline__ void ldm_x4(uint32_t (&r)[4], uint32_t addr) {
    asm volatile("ldmatrix.sync.aligned.m8n8.x4.shared.b16 {%0,%1,%2,%3}, [%4];"
        : "=r"(r[0]), "=r"(r[1]), "=r"(r[2]), "=r"(r[3]) : "r"(addr));
}
__device__ __forceinline__ void ldm_x2(uint32_t (&r)[2], uint32_t addr) {
    asm volatile("ldmatrix.sync.aligned.m8n8.x2.shared.b16 {%0,%1}, [%2];"
        : "=r"(r[0]), "=r"(r[1]) : "r"(addr));
}
__device__ __forceinline__ void mma_bf16(float (&d)[4], const uint32_t (&a)[4],
                                         const uint32_t (&b)[2]) {
    asm volatile("mma.sync.aligned.m16n8k16.row.col.f32.bf16.bf16.f32 "
        "{%0,%1,%2,%3}, {%4,%5,%6,%7}, {%8,%9}, {%0,%1,%2,%3};"
        : "+f"(d[0]), "+f"(d[1]), "+f"(d[2]), "+f"(d[3])
        : "r"(a[0]), "r"(a[1]), "r"(a[2]), "r"(a[3]), "r"(b[0]), "r"(b[1]));
}

// ---------------------------------------------------------------- warp-MMA GEMM
// CTA: 256 threads (8 warps), out tile 128(M) x 128(N). Warp tile 64x32.
// K chunks of 16; smem: A/B hi/lo bf16, rows padded to 48B; double-buffered.
// 3-pass hi/lo split: acc += Ah*Bh + Ah*Bl + Al*Bh  (fp32 accumulators).
#define RSB   48                       // smem row stride (bytes) per 16-k bf16 row
#define SEG   6144                     // 128 rows * 48B
#define BUFB  (4 * SEG)                // AH AL BH BL
// MODE: 0=OB 1=K1 2=K2 3=K3 4=K4
template<int MODE>
__global__ void __launch_bounds__(256)
tgemm(const float* __restrict__ A1, int lda1,
      const float* __restrict__ A2, int lda2,
      const float* __restrict__ W1, const float* __restrict__ W2,
      const float* __restrict__ bias1, const float* __restrict__ bias2,
      const float* __restrict__ nz1, const float* __restrict__ nz2,
      float* __restrict__ o0, float* __restrict__ o1, float* __restrict__ o2,
      float* __restrict__ o3, float* __restrict__ o4, float* __restrict__ o5,
      int t)
{
    __shared__ __align__(16) char smem[2 * BUFB];    // 48 KB
    const uint32_t sbase = smem_u32(smem);
    const int tid = threadIdx.x;
    const int lane = tid & 31, wid = tid >> 5;
    const int wm = wid & 1, wn = wid >> 1;           // warp grid 2(M) x 4(N)
    const int n0 = blockIdx.x * 128, m0 = blockIdx.y * 128;
    constexpr int NK = (MODE == 1) ? 10 : 64;        // K = 160 or 1024

    // ---- per-CTA A source ----
    const float* Ap = A1; int Alda = lda1;
    if (MODE == 2) { bool isX = (n0 < 3072); Ap = isX ? (const float*)g_x : A2; Alda = isX ? 1024 : lda2; }
    if (MODE == 4) { Ap = (const float*)g_HPQ + (n0 >> 8) * 1024; Alda = 2048; }

    // ---- staging ----
    uint4 sAh, sAl, sBh, sBl;
    const int lrow = tid >> 1, lhalf = tid & 1;      // 128 rows x 2 halves

    auto ldg = [&](int c) {
        float va[8], vb[8];
        const int kk = c * 16 + lhalf * 8;
        // A rows
        if (MODE == 1) {
            if (kk < 128) {
#pragma unroll
                for (int j = 0; j < 8; j++) va[j] = A1[(size_t)(m0 + lrow) * lda1 + kk + j];
            } else {
#pragma unroll
                for (int j = 0; j < 8; j++) va[j] = A2[(size_t)(m0 + lrow) * lda2 + kk - 128 + j];
            }
        } else {
#pragma unroll
            for (int j = 0; j < 8; j++) va[j] = Ap[(size_t)(m0 + lrow) * Alda + kk + j];
        }
        // B rows (weights, [n][k] row-major => mma row.col with plain ldmatrix)
        const int ni = n0 + lrow;
        const float* wp;
        if (MODE == 0)      wp = W1 + (size_t)ni * 2048 + 1024 + kk;
        else if (MODE == 1) wp = W1 + (size_t)ni * 160 + kk;
        else if (MODE == 2) wp = (ni < 3072) ? (W1 + (size_t)ni * 1024 + kk)
                                             : (W2 + (size_t)(ni - 3072) * 1024 + kk);
        else if (MODE == 3) wp = (ni < 1024) ? (W1 + (size_t)ni * 1024 + kk)
                                             : (W2 + (size_t)(ni - 1024) * 2048 + kk);
        else { // K4: mu/std interleave permutation baked into B rows
            int side = ni >> 8, cc = ni & 255;
            int row = (cc >> 1) + (cc & 1) * 128;
            wp = (side ? W2 : W1) + (size_t)row * 1024 + kk;
        }
#pragma unroll
        for (int j = 0; j < 8; j++) vb[j] = wp[j];
        cvt_pack8(va, sAh, sAl);
        cvt_pack8(vb, sBh, sBl);
    };
    auto sts = [&](int b) {
        char* bb = smem + b * BUFB;
        const int off = lrow * RSB + lhalf * 16;
        *(uint4*)(bb + off)           = sAh;
        *(uint4*)(bb + SEG + off)     = sAl;
        *(uint4*)(bb + 2 * SEG + off) = sBh;
        *(uint4*)(bb + 3 * SEG + off) = sBl;
    };

    float acc[4][4][4];
#pragma unroll
    for (int i = 0; i < 4; i++)
#pragma unroll
        for (int j = 0; j < 4; j++)
#pragma unroll
            for (int k = 0; k < 4; k++) acc[i][j][k] = 0.0f;

    const int arow = lane & 15, ak = lane >> 4;       // ldmatrix x4 lane addressing
    const int brow = lane & 7,  bk = (lane >> 3) & 1; // ldmatrix x2 lane addressing

    ldg(0); sts(0);
    __syncthreads();

    for (int c = 0; c < NK; c++) {
        const int b = c & 1;
        if (c + 1 < NK) ldg(c + 1);

        const uint32_t sA = sbase + b * BUFB;
        const uint32_t sB = sA + 2 * SEG;
        uint32_t ah[4][4], al[4][4], bh[4][2], bl[4][2];
#pragma unroll
        for (int mt = 0; mt < 4; mt++) {
            uint32_t ra = (uint32_t)((wm * 64 + mt * 16 + arow) * RSB + ak * 16);
            ldm_x4(ah[mt], sA + ra);
            ldm_x4(al[mt], sA + SEG + ra);
        }
#pragma unroll
        for (int nt = 0; nt < 4; nt++) {
            uint32_t rb = (uint32_t)((wn * 32 + nt * 8 + brow) * RSB + bk * 16);
            ldm_x2(bh[nt], sB + rb);
            ldm_x2(bl[nt], sB + SEG + rb);
        }
#pragma unroll
        for (int mt = 0; mt < 4; mt++)
#pragma unroll
            for (int nt = 0; nt < 4; nt++) {
                mma_bf16(acc[mt][nt], ah[mt], bh[nt]);
                mma_bf16(acc[mt][nt], ah[mt], bl[nt]);
                mma_bf16(acc[mt][nt], al[mt], bh[nt]);
            }
        __syncthreads();
        if (c + 1 < NK) { sts(b ^ 1); __syncthreads(); }
    }

    // ---------------- epilogue (register accumulators) ----------------------
    const int mrow = m0 + wm * 64 + (lane >> 2);       // + mt*16 (+8 for hi half)
    const int ncol = n0 + wn * 32 + (lane & 3) * 2;    // + nt*8 (+1 for odd)
#pragma unroll
    for (int mt = 0; mt < 4; mt++) {
#pragma unroll
        for (int nt = 0; nt < 4; nt++) {
            const float* d = acc[mt][nt];
#pragma unroll
            for (int hh = 0; hh < 2; hh++) {
                const int m = mrow + mt * 16 + hh * 8;
                const float v0 = d[hh * 2], v1 = d[hh * 2 + 1];
                const int n = ncol + nt * 8;
                if (MODE == 0) {
                    g_OB[(size_t)m * 1024 + n]     = v0 + bias1[n];
                    g_OB[(size_t)m * 1024 + n + 1] = v1 + bias1[n + 1];
                } else if (MODE == 1) {
                    g_x[m * 1024 + n]     = fmaxf(v0 + bias1[n], 0.0f);
                    g_x[m * 1024 + n + 1] = fmaxf(v1 + bias1[n + 1], 0.0f);
                } else if (MODE == 2) {
                    float bi0 = (n < 3072) ? bias1[n]     : bias2[n - 3072];
                    float bi1 = (n < 3072) ? bias1[n + 1] : bias2[n + 1 - 3072];
                    g_G[(size_t)m * 6144 + n]     = v0 + bi0;
                    g_G[(size_t)m * 6144 + n + 1] = v1 + bi1;
                } else if (MODE == 3) {
                    float a0 = (n < 1024) ? bias1[n]
                                          : g_OB[((size_t)m * T1_ + t) * 1024 + n - 1024];
                    float a1 = (n < 1024) ? bias1[n + 1]
                                          : g_OB[((size_t)m * T1_ + t) * 1024 + n + 1 - 1024];
                    g_HPQ[(size_t)m * 2048 + n]     = fmaxf(v0 + a0, 0.0f);
                    g_HPQ[(size_t)m * 2048 + n + 1] = fmaxf(v1 + a1, 0.0f);
                } else { // K4: (even,odd) = (mu, pre-softplus) pair
                    const int side = n >> 8;
                    const float* bias = side ? bias2 : bias1;
                    const float* nz   = side ? nz2 : nz1;
                    float* os  = side ? o3 : o0;
                    float* omu = side ? o4 : o1;
                    float* ost = side ? o5 : o2;
                    const int pp = (n & 255) >> 1;
                    float mu = v0 + bias[pp];
                    float h2 = v1 + bias[pp + 128];
                    float sd = ((h2 > 20.0f) ? h2 : log1pf(expf(h2))) + 0.1f;
                    size_t o = (size_t)m * SSTRIDE + pp;
                    float ep = nz[o];
                    omu[o] = mu;
                    ost[o] = sd;
                    os [o] = mu + sd * ep;
                }
            }
        }
    }
}

// ---------------- fused GRU gates -> b1 = Beliefs[:,t,:], float4 -------------
__device__ __forceinline__ float gate1(float ir, float iz, float in_,
                                       float hr, float hz, float hn, float h) {
    float r  = 1.0f / (1.0f + expf(-(ir + hr)));
    float z  = 1.0f / (1.0f + expf(-(iz + hz)));
    float nn = tanhf(in_ + r * hn);
    return (1.0f - z) * nn + z * h;
}
__global__ void k2_gates(const float* __restrict__ bprev, int bs,
                         float* __restrict__ bout)
{
    int idx = blockIdx.x * 256 + threadIdx.x;     // 65536 threads
    int m = idx >> 8, q = (idx & 255) << 2;
    const float* g = g_G + (size_t)m * 6144;
    float4 ir  = *(const float4*)(g + q);
    float4 iz  = *(const float4*)(g + 1024 + q);
    float4 in_ = *(const float4*)(g + 2048 + q);
    float4 hr  = *(const float4*)(g + 3072 + q);
    float4 hz  = *(const float4*)(g + 4096 + q);
    float4 hn  = *(const float4*)(g + 5120 + q);
    float4 h   = *(const float4*)(bprev + (size_t)m * bs + q);
    float4 o;
    o.x = gate1(ir.x, iz.x, in_.x, hr.x, hz.x, hn.x, h.x);
    o.y = gate1(ir.y, iz.y, in_.y, hr.y, hz.y, hn.y, h.y);
    o.z = gate1(ir.z, iz.z, in_.z, hr.z, hz.z, hn.z, h.z);
    o.w = gate1(ir.w, iz.w, in_.w, hr.w, hz.w, hn.w, h.w);
    *(float4*)(bout + (size_t)m * BSTRIDE + q) = o;
}

// ---------------------------------------------------------------- host
extern "C" void kernel_launch(void* const* d_in, const int* in_sizes, int n_in,
                              void* d_out, int out_size)
{
    (void)in_sizes; (void)n_in; (void)out_size;
    const float* s0     = (const float*)d_in[0];
    const float* b0     = (const float*)d_in[1];
    const float* Act    = (const float*)d_in[2];
    const float* Obs    = (const float*)d_in[3];
    const float* np     = (const float*)d_in[4];
    const float* nq     = (const float*)d_in[5];
    const float* W_sa   = (const float*)d_in[6];
    const float* b_sa   = (const float*)d_in[7];
    const float* W_ih   = (const float*)d_in[8];
    const float* W_hh   = (const float*)d_in[9];
    const float* b_ih   = (const float*)d_in[10];
    const float* b_hh   = (const float*)d_in[11];
    const float* W_bpri = (const float*)d_in[12];
    const float* b_bpri = (const float*)d_in[13];
    const float* W_spri = (const float*)d_in[14];
    const float* b_spri = (const float*)d_in[15];
    const float* W_bpos = (const float*)d_in[16];
    const float* b_bpos = (const float*)d_in[17];
    const float* W_spos = (const float*)d_in[18];
    const float* b_spos = (const float*)d_in[19];

    float* out   = (float*)d_out;
    float* O_b   = out;
    float* O_sp  = O_b   + O_B_SZ;
    float* O_mup = O_sp  + O_S_SZ;
    float* O_stp = O_mup + O_S_SZ;
    float* O_sq  = O_stp + O_S_SZ;
    float* O_muq = O_sq  + O_S_SZ;
    float* O_stq = O_muq + O_S_SZ;

    // Hoisted observation projection: g_OB = Obs @ W_bpos[:,1024:]^T + b_bpos
    tgemm<0><<<dim3(8, 256), 256>>>(Obs, 1024, nullptr, 0, W_bpos, nullptr,
                                    b_bpos, nullptr, nullptr, nullptr,
                                    nullptr, nullptr, nullptr, nullptr, nullptr, nullptr, 0);

    for (int t = 0; t < T1_; t++) {
        const float* sprev = t ? (O_sq + (size_t)(t - 1) * S_) : s0;
        const int    ss    = t ? SSTRIDE : S_;
        const float* bprev = t ? (O_b + (size_t)(t - 1) * H_) : b0;
        const int    bs    = t ? BSTRIDE : H_;
        float* b1 = O_b + (size_t)t * H_;

        tgemm<1><<<dim3(8, 2),  256>>>(sprev, ss, Act + (size_t)t * A_, T1_ * A_,
                                       W_sa, nullptr, b_sa, nullptr, nullptr, nullptr,
                                       nullptr, nullptr, nullptr, nullptr, nullptr, nullptr, t);
        tgemm<2><<<dim3(48, 2), 256>>>(nullptr, 0, bprev, bs,
                                       W_ih, W_hh, b_ih, b_hh, nullptr, nullptr,
                                       nullptr, nullptr, nullptr, nullptr, nullptr, nullptr, t);
        k2_gates<<<256, 256>>>(bprev, bs, b1);
        tgemm<3><<<dim3(16, 2), 256>>>(b1, BSTRIDE, nullptr, 0,
                                       W_bpri, W_bpos, b_bpri, nullptr, nullptr, nullptr,
                                       nullptr, nullptr, nullptr, nullptr, nullptr, nullptr, t);
        tgemm<4><<<dim3(4, 2),  256>>>(nullptr, 0, nullptr, 0,
                                       W_spri, W_spos, b_spri, b_spos,
                                       np + (size_t)t * S_, nq + (size_t)t * S_,
                                       O_sp  + (size_t)t * S_, O_mup + (size_t)t * S_,
                                       O_stp + (size_t)t * S_, O_sq  + (size_t)t * S_,
                                       O_muq + (size_t)t * S_, O_stq + (size_t)t * S_, t);
    }
}